// round 10
// baseline (speedup 1.0000x reference)
#include <cuda_runtime.h>
#include <cstdint>

#define Bv 8192
#define Mv 512
#define Ov 128

// ---- smem byte offsets ----
#define SM_STAGE 0        // fp32 x stage (one full batch): 512*64*4 = 131072
#define SM_XH    131072   // x bf16: 512 rows * 128B (chunk-XOR swizzled) = 65536
#define SM_LN    196608   // lam^T bf16 (o-row-permuted): 128 rows * 128B = 16384
#define SM_SRED  212992   // 32 x 64 f32 column-sum partials = 8192
#define SM_S     221184   // s[64] f32 = 256
#define SM_POOL  221440   // pooled[128] f32 = 512
#define SMEM_BYTES 221952

__device__ __forceinline__ uint32_t cvta_smem(const void* p) {
    uint32_t a;
    asm("{ .reg .u64 t; cvta.to.shared.u64 t, %1; cvt.u32.u64 %0, t; }" : "=r"(a) : "l"(p));
    return a;
}

__device__ __forceinline__ uint32_t pack_bf16x2(float lo, float hi) {
    uint32_t r;
    asm("cvt.rn.bf16x2.f32 %0, %1, %2;" : "=r"(r) : "f"(hi), "f"(lo));
    return r;
}

__device__ __forceinline__ void ldsm4(uint32_t addr, uint32_t r[4]) {
    asm volatile("ldmatrix.sync.aligned.m8n8.x4.shared.b16 {%0,%1,%2,%3}, [%4];"
        : "=r"(r[0]), "=r"(r[1]), "=r"(r[2]), "=r"(r[3]) : "r"(addr));
}

__device__ __forceinline__ void hmma(float d[4], const uint32_t a[4], const uint32_t b[2]) {
    asm volatile("mma.sync.aligned.m16n8k16.row.col.f32.bf16.bf16.f32 "
        "{%0,%1,%2,%3}, {%4,%5,%6,%7}, {%8,%9}, {%0,%1,%2,%3};"
        : "+f"(d[0]), "+f"(d[1]), "+f"(d[2]), "+f"(d[3])
        : "r"(a[0]), "r"(a[1]), "r"(a[2]), "r"(a[3]), "r"(b[0]), "r"(b[1]));
}

__device__ __forceinline__ void cp16(uint32_t dst, const void* src) {
    asm volatile("cp.async.cg.shared.global [%0], [%1], 16;"
        :: "r"(dst), "l"(src) : "memory");
}

__device__ __forceinline__ void stg_cs4(float* p, float a, float b, float c, float d) {
    asm volatile("st.global.cs.v4.f32 [%0], {%1,%2,%3,%4};"
        :: "l"(p), "f"(a), "f"(b), "f"(c), "f"(d) : "memory");
}

extern __shared__ char smem[];

__global__ __launch_bounds__(512, 1)
void eq_mma7_kernel(const float* __restrict__ x,
                    const float* __restrict__ lam,
                    const float* __restrict__ gam,
                    float* __restrict__ out)
{
    const uint32_t sb = cvta_smem(smem);
    const int t = threadIdx.x;
    const int grid = gridDim.x;
    const int w = t >> 5, lane = t & 31, g = lane >> 2, tg = lane & 3;

    // ---- prologue: kick off first batch's x load, then stage lam ----
    if ((int)blockIdx.x < Bv) {
        const char* src = (const char*)(x + (size_t)blockIdx.x * (Mv * 64));
        #pragma unroll
        for (int j = 0; j < 16; j++)
            cp16(sb + SM_STAGE + (uint32_t)((j * 512 + t) * 16),
                 src + (j * 512 + t) * 16);
    }
    asm volatile("cp.async.commit_group;" ::: "memory");

    // lam^T -> bf16 smem, o-row-permuted within each 16-row group
    {
        const int o = t & 127;
        const int r15 = o & 15;
        const int orow = (o & ~15) | (((r15 & 2) << 2) | ((r15 >> 2) << 1) | (r15 & 1));
        const int q = t >> 7;             // 0..3, 8 f-pairs each
        #pragma unroll
        for (int j = 0; j < 8; j++) {
            const int fp = q * 8 + j;
            const float v0 = lam[(2 * fp) * Ov + o];
            const float v1 = lam[(2 * fp + 1) * Ov + o];
            const uint32_t h = pack_bf16x2(v0, v1);
            const uint32_t off = (uint32_t)(orow * 128
                + (((fp >> 2) ^ (orow & 7)) << 4) + (fp & 3) * 4);
            *(uint32_t*)(smem + SM_LN + off) = h;
        }
    }

    // fragment-address constants
    const int f4 = t & 15, tm = t >> 4;          // convert-phase mapping
    const int chunk = f4 >> 1, half = f4 & 1;
    const int am = lane & 15, acs = lane >> 4, asw = am & 7;
    const int bo = (lane & 7) | ((lane & 16) >> 1);
    const int bcs = (lane >> 3) & 1, bsw = bo & 7;
    const float* poolp = (const float*)(smem + SM_POOL);
    const int m0 = 32 * w;                        // warp's 32 rows

    for (int b = blockIdx.x; b < Bv; b += grid) {
        // ---- wait for staged x[b]; also fences previous batch's MMA reads ----
        asm volatile("cp.async.wait_group 0;" ::: "memory");
        __syncthreads();

        // ---- convert: fp32 stage -> bf16 XH (swizzled) + column sums ----
        {
            float4 s4 = make_float4(0.f, 0.f, 0.f, 0.f);
            #pragma unroll 4
            for (int i = 0; i < 16; i++) {
                const int m = tm + 32 * i;
                const float4 v = *(const float4*)(smem + SM_STAGE + (m * 16 + f4) * 16);
                s4.x += v.x; s4.y += v.y; s4.z += v.z; s4.w += v.w;
                const uint32_t h01 = pack_bf16x2(v.x, v.y);
                const uint32_t h23 = pack_bf16x2(v.z, v.w);
                const uint32_t off = (uint32_t)(m * 128
                    + ((chunk ^ (m & 7)) << 4) + half * 8);
                *(uint2*)(smem + SM_XH + off) = make_uint2(h01, h23);
            }
            *(float4*)(smem + SM_SRED + (tm * 64 + f4 * 4) * 4) = s4;
        }
        __syncthreads();   // XH + sred ready; stage free for next prefetch

        // ---- prefetch next batch's x while this batch computes/stores ----
        if (b + grid < Bv) {
            const char* src = (const char*)(x + (size_t)(b + grid) * (Mv * 64));
            #pragma unroll
            for (int j = 0; j < 16; j++)
                cp16(sb + SM_STAGE + (uint32_t)((j * 512 + t) * 16),
                     src + (j * 512 + t) * 16);
        }
        asm volatile("cp.async.commit_group;" ::: "memory");

        // ---- s[f] then pooled[o] (exact fp32; gam L2-resident after wave 1) ----
        if (t < 64) {
            float v = 0.f;
            #pragma unroll
            for (int r = 0; r < 32; r++)
                v += *(const float*)(smem + SM_SRED + (r * 64 + t) * 4);
            *(float*)(smem + SM_S + t * 4) = v;
        }
        __syncthreads();
        if (t < 128) {
            float p = 0.f;
            #pragma unroll 8
            for (int f = 0; f < 64; f++)
                p += *(const float*)(smem + SM_S + f * 4) * gam[f * Ov + t];
            *(float*)(smem + SM_POOL + t * 4) = p;
        }
        __syncthreads();

        // ---- MMA: warp w owns rows 32w..32w+31 ----
        float* outb = out + (size_t)b * (Mv * Ov);

        uint32_t afr[4][2][4];
        #pragma unroll
        for (int k = 0; k < 4; k++) {
            const uint32_t aadr = sb + SM_XH + (uint32_t)((m0 + am) * 128
                                + ((((k << 1) | acs) ^ asw) << 4));
            ldsm4(aadr, afr[k][0]);
            ldsm4(aadr + 16 * 128, afr[k][1]);
        }

        #pragma unroll 1
        for (int nh = 0; nh < 2; nh++) {
            const int o0 = nh * 64;
            float acc[2][8][4];
            #pragma unroll
            for (int i = 0; i < 2; i++)
                #pragma unroll
                for (int j = 0; j < 8; j++)
                    #pragma unroll
                    for (int c = 0; c < 4; c++)
                        acc[i][j][c] = 0.f;

            #pragma unroll
            for (int k = 0; k < 4; k++)
                #pragma unroll
                for (int np = 0; np < 4; np++) {
                    uint32_t bf[4];
                    ldsm4(sb + SM_LN + (uint32_t)((o0 + np * 16 + bo) * 128
                            + ((((k << 1) | bcs) ^ bsw) << 4)), bf);
                    hmma(acc[0][2 * np],     afr[k][0], bf);
                    hmma(acc[0][2 * np + 1], afr[k][0], bf + 2);
                    hmma(acc[1][2 * np],     afr[k][1], bf);
                    hmma(acc[1][2 * np + 1], afr[k][1], bf + 2);
                }

            #pragma unroll
            for (int np = 0; np < 4; np++) {
                const int col = o0 + np * 16 + 4 * tg;
                const float4 pl = *(const float4*)&poolp[col];
                #pragma unroll
                for (int mt = 0; mt < 2; mt++) {
                    const float* a0 = acc[mt][2 * np];
                    const float* a1 = acc[mt][2 * np + 1];
                    float* r0 = outb + (size_t)(m0 + mt * 16 + g) * Ov + col;
                    stg_cs4(r0,
                            fmaxf(a0[0] - pl.x, 0.f), fmaxf(a0[1] - pl.y, 0.f),
                            fmaxf(a1[0] - pl.z, 0.f), fmaxf(a1[1] - pl.w, 0.f));
                    stg_cs4(r0 + 8 * Ov,
                            fmaxf(a0[2] - pl.x, 0.f), fmaxf(a0[3] - pl.y, 0.f),
                            fmaxf(a1[2] - pl.z, 0.f), fmaxf(a1[3] - pl.w, 0.f));
                }
            }
        }
    }
}

extern "C" void kernel_launch(void* const* d_in, const int* in_sizes, int n_in,
                              void* d_out, int out_size)
{
    (void)in_sizes; (void)n_in; (void)out_size;
    const float* x   = (const float*)d_in[0];
    const float* lam = (const float*)d_in[1];
    const float* gam = (const float*)d_in[2];
    float* out = (float*)d_out;

    int nsm = 0;
    if (cudaDeviceGetAttribute(&nsm, cudaDevAttrMultiProcessorCount, 0) != cudaSuccess
        || nsm <= 0)
        nsm = 148;
    if (nsm > Bv) nsm = Bv;

    cudaFuncSetAttribute(eq_mma7_kernel, cudaFuncAttributeMaxDynamicSharedMemorySize,
                         SMEM_BYTES);
    eq_mma7_kernel<<<nsm, 512, SMEM_BYTES>>>(x, lam, gam, out);
}

// round 12
// speedup vs baseline: 1.1747x; 1.1747x over previous
#include <cuda_runtime.h>
#include <cstdint>

#define Bv 8192
#define Mv 512
#define Ov 128

// ---- smem byte offsets ----
#define SM_XH   0        // x bf16: 512 rows * 128B (chunk-XOR swizzled) = 65536
#define SM_LN   65536    // lam^T bf16 (o-row-permuted): 128 rows * 128B = 16384
#define SM_SRED 81920    // 16 x 64 f32 partial column sums = 4096
#define SM_S    86016    // s[64] f32 = 256
#define SM_POOL 86272    // pooled[128] f32 = 512
#define SMEM_BYTES 86784

__device__ __forceinline__ uint32_t cvta_smem(const void* p) {
    uint32_t a;
    asm("{ .reg .u64 t; cvta.to.shared.u64 t, %1; cvt.u32.u64 %0, t; }" : "=r"(a) : "l"(p));
    return a;
}

__device__ __forceinline__ uint32_t pack_bf16x2(float lo, float hi) {
    uint32_t r;
    asm("cvt.rn.bf16x2.f32 %0, %1, %2;" : "=r"(r) : "f"(hi), "f"(lo));
    return r;
}

__device__ __forceinline__ void ldsm4(uint32_t addr, uint32_t r[4]) {
    asm volatile("ldmatrix.sync.aligned.m8n8.x4.shared.b16 {%0,%1,%2,%3}, [%4];"
        : "=r"(r[0]), "=r"(r[1]), "=r"(r[2]), "=r"(r[3]) : "r"(addr));
}

__device__ __forceinline__ void hmma(float d[4], const uint32_t a[4], const uint32_t b[2]) {
    asm volatile("mma.sync.aligned.m16n8k16.row.col.f32.bf16.bf16.f32 "
        "{%0,%1,%2,%3}, {%4,%5,%6,%7}, {%8,%9}, {%0,%1,%2,%3};"
        : "+f"(d[0]), "+f"(d[1]), "+f"(d[2]), "+f"(d[3])
        : "r"(a[0]), "r"(a[1]), "r"(a[2]), "r"(a[3]), "r"(b[0]), "r"(b[1]));
}

__device__ __forceinline__ float4 ldg_cs4(const float4* p) {
    float4 v;
    asm volatile("ld.global.cs.v4.f32 {%0,%1,%2,%3}, [%4];"
        : "=f"(v.x), "=f"(v.y), "=f"(v.z), "=f"(v.w) : "l"(p));
    return v;
}
__device__ __forceinline__ void stg_cs4(float* p, float a, float b, float c, float d) {
    asm volatile("st.global.cs.v4.f32 [%0], {%1,%2,%3,%4};"
        :: "l"(p), "f"(a), "f"(b), "f"(c), "f"(d) : "memory");
}

extern __shared__ char smem[];

__global__ __launch_bounds__(256, 2)
void eq_mma9_kernel(const float* __restrict__ x,
                    const float* __restrict__ lam,
                    const float* __restrict__ gam,
                    float* __restrict__ out)
{
    const uint32_t sb = cvta_smem(smem);
    const int t = threadIdx.x;
    const int b = blockIdx.x;
    const int w = t >> 5, lane = t & 31, g = lane >> 2, tg = lane & 3;

    // ---- Phase A: x[b] fp32 -> bf16 smem (swizzled) + partial column sums ----
    {
        const float4* xg = (const float4*)(x + (size_t)b * (Mv * 64));
        const int f4 = t & 15;            // which float4 within a row
        const int tm = t >> 4;            // row phase (0..15)
        const int chunk = f4 >> 1, half = f4 & 1;
        float4 s4 = make_float4(0.f, 0.f, 0.f, 0.f);
        #pragma unroll 8
        for (int i = 0; i < 32; i++) {
            const int m = tm + 16 * i;
            const float4 v = ldg_cs4(&xg[m * 16 + f4]);
            s4.x += v.x; s4.y += v.y; s4.z += v.z; s4.w += v.w;
            const uint32_t h01 = pack_bf16x2(v.x, v.y);
            const uint32_t h23 = pack_bf16x2(v.z, v.w);
            const uint32_t off = (uint32_t)(m * 128 + ((chunk ^ (m & 7)) << 4) + half * 8);
            *(uint2*)(smem + SM_XH + off) = make_uint2(h01, h23);
        }
        *(float4*)(smem + SM_SRED + (tm * 64 + f4 * 4) * 4) = s4;
    }

    // ---- Phase B: lam^T -> bf16 smem, o-row-permuted within 16-row groups ----
    {
        const int o = t & 127;
        const int r15 = o & 15;
        const int orow = (o & ~15) | (((r15 & 2) << 2) | ((r15 >> 2) << 1) | (r15 & 1));
        const int q = t >> 7;
        #pragma unroll 4
        for (int j = 0; j < 16; j++) {
            const int fp = q * 16 + j;
            const float v0 = lam[(2 * fp) * Ov + o];
            const float v1 = lam[(2 * fp + 1) * Ov + o];
            const uint32_t h = pack_bf16x2(v0, v1);
            const uint32_t off = (uint32_t)(orow * 128
                + (((fp >> 2) ^ (orow & 7)) << 4) + (fp & 3) * 4);
            *(uint32_t*)(smem + SM_LN + off) = h;
        }
    }
    __syncthreads();   // XH + LN + SRED all visible

    // fragment-address constants
    const int am = lane & 15, acs = lane >> 4, asw = am & 7;
    const int bo = (lane & 7) | ((lane & 16) >> 1);
    const int bcs = (lane >> 3) & 1, bsw = bo & 7;
    const float* poolp = (const float*)(smem + SM_POOL);
    float* outb = out + (size_t)b * (Mv * Ov);

    // ---- all warps: preload mp=0 A fragments (hide LDS latency) ----
    uint32_t afr[4][2][4];
    {
        const uint32_t arow_off = (uint32_t)((w * 64 + am) * 128);
        #pragma unroll
        for (int k = 0; k < 4; k++) {
            const uint32_t aadr = sb + SM_XH + arow_off
                                + (uint32_t)((((k << 1) | acs) ^ asw) << 4);
            ldsm4(aadr, afr[k][0]);
            ldsm4(aadr + 16 * 128, afr[k][1]);
        }
    }

    // ---- pooled producer (warps 0-3) overlapped with consumers' first MMA ----
    if (t < 128) {
        if (t < 64) {
            float v = 0.f;
            #pragma unroll
            for (int r = 0; r < 16; r++)
                v += *(const float*)(smem + SM_SRED + (r * 64 + t) * 4);
            *(float*)(smem + SM_S + t * 4) = v;
        }
        asm volatile("bar.sync 1, 128;" ::: "memory");
        float p = 0.f;
        #pragma unroll 8
        for (int f = 0; f < 64; f++)
            p += *(const float*)(smem + SM_S + f * 4) * __ldg(&gam[f * Ov + t]);
        *(float*)(smem + SM_POOL + t * 4) = p;
        // producer-group sync: ALL pooled entries visible to producers
        // before any producer reads poolp in its own epilogue (R11 race fix)
        asm volatile("bar.sync 1, 128;" ::: "memory");
        asm volatile("bar.arrive 2, 256;" ::: "memory");   // release warps 4-7
    }

    // ---- MMA: warp w owns rows 64w..64w+63, two 32-row sub-passes ----
    #pragma unroll 1
    for (int mp = 0; mp < 2; mp++) {
        const int m0 = w * 64 + mp * 32;

        if (mp == 1) {   // load second sub-pass A fragments
            const uint32_t arow_off = (uint32_t)((m0 + am) * 128);
            #pragma unroll
            for (int k = 0; k < 4; k++) {
                const uint32_t aadr = sb + SM_XH + arow_off
                                    + (uint32_t)((((k << 1) | acs) ^ asw) << 4);
                ldsm4(aadr, afr[k][0]);
                ldsm4(aadr + 16 * 128, afr[k][1]);
            }
        }

        #pragma unroll 1
        for (int nh = 0; nh < 2; nh++) {
            const int o0 = nh * 64;
            float acc[2][8][4];
            #pragma unroll
            for (int i = 0; i < 2; i++)
                #pragma unroll
                for (int j = 0; j < 8; j++)
                    #pragma unroll
                    for (int c = 0; c < 4; c++)
                        acc[i][j][c] = 0.f;

            #pragma unroll
            for (int k = 0; k < 4; k++)
                #pragma unroll
                for (int np = 0; np < 4; np++) {
                    uint32_t bf[4];
                    ldsm4(sb + SM_LN + (uint32_t)((o0 + np * 16 + bo) * 128
                            + ((((k << 1) | bcs) ^ bsw) << 4)), bf);
                    hmma(acc[0][2 * np],     afr[k][0], bf);
                    hmma(acc[0][2 * np + 1], afr[k][0], bf + 2);
                    hmma(acc[1][2 * np],     afr[k][1], bf);
                    hmma(acc[1][2 * np + 1], afr[k][1], bf + 2);
                }

            // consumers (warps 4-7) wait for pooled once, before first store
            if (t >= 128 && mp == 0 && nh == 0)
                asm volatile("bar.sync 2, 256;" ::: "memory");

            #pragma unroll
            for (int np = 0; np < 4; np++) {
                const int col = o0 + np * 16 + 4 * tg;
                const float4 pl = *(const float4*)&poolp[col];
                #pragma unroll
                for (int mt = 0; mt < 2; mt++) {
                    const float* a0 = acc[mt][2 * np];
                    const float* a1 = acc[mt][2 * np + 1];
                    float* r0 = outb + (size_t)(m0 + mt * 16 + g) * Ov + col;
                    stg_cs4(r0,
                            fmaxf(a0[0] - pl.x, 0.f), fmaxf(a0[1] - pl.y, 0.f),
                            fmaxf(a1[0] - pl.z, 0.f), fmaxf(a1[1] - pl.w, 0.f));
                    stg_cs4(r0 + 8 * Ov,
                            fmaxf(a0[2] - pl.x, 0.f), fmaxf(a0[3] - pl.y, 0.f),
                            fmaxf(a1[2] - pl.z, 0.f), fmaxf(a1[3] - pl.w, 0.f));
                }
            }
        }
    }
}

extern "C" void kernel_launch(void* const* d_in, const int* in_sizes, int n_in,
                              void* d_out, int out_size)
{
    (void)in_sizes; (void)n_in; (void)out_size;
    const float* x   = (const float*)d_in[0];
    const float* lam = (const float*)d_in[1];
    const float* gam = (const float*)d_in[2];
    float* out = (float*)d_out;

    cudaFuncSetAttribute(eq_mma9_kernel, cudaFuncAttributeMaxDynamicSharedMemorySize,
                         SMEM_BYTES);
    eq_mma9_kernel<<<Bv, 256, SMEM_BYTES>>>(x, lam, gam, out);
}

// round 13
// speedup vs baseline: 1.1941x; 1.0165x over previous
#include <cuda_runtime.h>
#include <cstdint>

#define Bv 8192
#define Mv 512
#define Ov 128
#define NCONC 296   // 148 SMs x 2 CTAs/SM = one wave

// ---- smem byte offsets ----
#define SM_XH   0        // x bf16: 512 rows * 128B (chunk-XOR swizzled) = 65536
#define SM_LN   65536    // lam^T bf16 (o-row-permuted): 128 rows * 128B = 16384
#define SM_SRED 81920    // 16 x 64 f32 partial column sums = 4096
#define SM_POOL 86016    // pooled[128] f32 = 512
#define SMEM_BYTES 86528

__device__ __forceinline__ uint32_t cvta_smem(const void* p) {
    uint32_t a;
    asm("{ .reg .u64 t; cvta.to.shared.u64 t, %1; cvt.u32.u64 %0, t; }" : "=r"(a) : "l"(p));
    return a;
}

__device__ __forceinline__ uint32_t pack_bf16x2(float lo, float hi) {
    uint32_t r;
    asm("cvt.rn.bf16x2.f32 %0, %1, %2;" : "=r"(r) : "f"(hi), "f"(lo));
    return r;
}

__device__ __forceinline__ void ldsm4(uint32_t addr, uint32_t r[4]) {
    asm volatile("ldmatrix.sync.aligned.m8n8.x4.shared.b16 {%0,%1,%2,%3}, [%4];"
        : "=r"(r[0]), "=r"(r[1]), "=r"(r[2]), "=r"(r[3]) : "r"(addr));
}

__device__ __forceinline__ void hmma(float d[4], const uint32_t a[4], const uint32_t b[2]) {
    asm volatile("mma.sync.aligned.m16n8k16.row.col.f32.bf16.bf16.f32 "
        "{%0,%1,%2,%3}, {%4,%5,%6,%7}, {%8,%9}, {%0,%1,%2,%3};"
        : "+f"(d[0]), "+f"(d[1]), "+f"(d[2]), "+f"(d[3])
        : "r"(a[0]), "r"(a[1]), "r"(a[2]), "r"(a[3]), "r"(b[0]), "r"(b[1]));
}

__device__ __forceinline__ float4 ldg_cs4(const float4* p) {
    float4 v;
    asm volatile("ld.global.cs.v4.f32 {%0,%1,%2,%3}, [%4];"
        : "=f"(v.x), "=f"(v.y), "=f"(v.z), "=f"(v.w) : "l"(p));
    return v;
}
__device__ __forceinline__ void stg_cs4(float* p, float a, float b, float c, float d) {
    asm volatile("st.global.cs.v4.f32 [%0], {%1,%2,%3,%4};"
        :: "l"(p), "f"(a), "f"(b), "f"(c), "f"(d) : "memory");
}

__device__ __forceinline__ void pref_l2(const void* p) {
    asm volatile("prefetch.global.L2 [%0];" :: "l"(p));
}

extern __shared__ char smem[];

__global__ __launch_bounds__(256, 2)
void eq_mma10_kernel(const float* __restrict__ x,
                     const float* __restrict__ lam,
                     const float* __restrict__ gam,
                     float* __restrict__ out)
{
    const uint32_t sb = cvta_smem(smem);
    const int t = threadIdx.x;
    const int b = blockIdx.x;
    const int w = t >> 5, lane = t & 31, g = lane >> 2, tg = lane & 3;

    // ---- Phase A: x[b] fp32 -> bf16 smem (swizzled) + partial column sums ----
    {
        const float4* xg = (const float4*)(x + (size_t)b * (Mv * 64));
        const int f4 = t & 15;            // which float4 within a row
        const int tm = t >> 4;            // row phase (0..15)
        const int chunk = f4 >> 1, half = f4 & 1;
        float4 s4 = make_float4(0.f, 0.f, 0.f, 0.f);
        #pragma unroll 8
        for (int i = 0; i < 32; i++) {
            const int m = tm + 16 * i;
            const float4 v = ldg_cs4(&xg[m * 16 + f4]);
            s4.x += v.x; s4.y += v.y; s4.z += v.z; s4.w += v.w;
            const uint32_t h01 = pack_bf16x2(v.x, v.y);
            const uint32_t h23 = pack_bf16x2(v.z, v.w);
            const uint32_t off = (uint32_t)(m * 128 + ((chunk ^ (m & 7)) << 4) + half * 8);
            *(uint2*)(smem + SM_XH + off) = make_uint2(h01, h23);
        }
        *(float4*)(smem + SM_SRED + (tm * 64 + f4 * 4) * 4) = s4;
    }

    // ---- prefetch next wave's x[b+NCONC] into (chip-shared) L2 ----
    // Reads for the next wave overlap THIS wave's MMA + store phase;
    // next wave's load phase then hits L2. 4 x 128B lines per thread.
    if (b + NCONC < Bv) {
        const char* nx = (const char*)(x + (size_t)(b + NCONC) * (Mv * 64));
        #pragma unroll
        for (int j = 0; j < 4; j++)
            pref_l2(nx + (t + 256 * j) * 128);
    }

    // ---- Phase B: lam^T -> bf16 smem, o-row-permuted within 16-row groups ----
    {
        const int o = t & 127;
        const int r15 = o & 15;
        const int orow = (o & ~15) | (((r15 & 2) << 2) | ((r15 >> 2) << 1) | (r15 & 1));
        const int q = t >> 7;
        #pragma unroll 4
        for (int j = 0; j < 16; j++) {
            const int fp = q * 16 + j;
            const float v0 = lam[(2 * fp) * Ov + o];
            const float v1 = lam[(2 * fp + 1) * Ov + o];
            const uint32_t h = pack_bf16x2(v0, v1);
            const uint32_t off = (uint32_t)(orow * 128
                + (((fp >> 2) ^ (orow & 7)) << 4) + (fp & 3) * 4);
            *(uint32_t*)(smem + SM_LN + off) = h;
        }
    }
    __syncthreads();

    // ---- finalize s[f] = sum_m x[m,f] ----
    if (t < 64) {
        float v = 0.f;
        #pragma unroll
        for (int r = 0; r < 16; r++)
            v += *(const float*)(smem + SM_SRED + (r * 64 + t) * 4);
        *(float*)(smem + SM_SRED + t * 4) = v;
    }
    __syncthreads();

    // ---- pooled[o] = sum_f s[f] * gam[f,o] (exact fp32) ----
    if (t < 128) {
        float p = 0.f;
        #pragma unroll
        for (int f = 0; f < 64; f++)
            p += *(const float*)(smem + SM_SRED + f * 4) * gam[f * Ov + t];
        *(float*)(smem + SM_POOL + t * 4) = p;
    }
    __syncthreads();

    // ---- Main: per-warp 64 rows x 128 cols, two 32-row sub-passes ----
    const int am = lane & 15, acs = lane >> 4, asw = am & 7;
    const int bo = (lane & 7) | ((lane & 16) >> 1);
    const int bcs = (lane >> 3) & 1, bsw = bo & 7;
    const float* poolp = (const float*)(smem + SM_POOL);
    float* outb = out + (size_t)b * (Mv * Ov);

    #pragma unroll 1
    for (int mp = 0; mp < 2; mp++) {
        const int m0 = w * 64 + mp * 32;
        const uint32_t arow_off = (uint32_t)((m0 + am) * 128);

        uint32_t afr[4][2][4];
        #pragma unroll
        for (int k = 0; k < 4; k++) {
            const uint32_t aadr = sb + SM_XH + arow_off
                                + (uint32_t)((((k << 1) | acs) ^ asw) << 4);
            ldsm4(aadr, afr[k][0]);
            ldsm4(aadr + 16 * 128, afr[k][1]);
        }

        #pragma unroll 1
        for (int nh = 0; nh < 2; nh++) {
            const int o0 = nh * 64;
            float acc[2][8][4];
            #pragma unroll
            for (int i = 0; i < 2; i++)
                #pragma unroll
                for (int j = 0; j < 8; j++)
                    #pragma unroll
                    for (int c = 0; c < 4; c++)
                        acc[i][j][c] = 0.f;

            #pragma unroll
            for (int k = 0; k < 4; k++)
                #pragma unroll
                for (int np = 0; np < 4; np++) {
                    uint32_t bf[4];
                    ldsm4(sb + SM_LN + (uint32_t)((o0 + np * 16 + bo) * 128
                            + ((((k << 1) | bcs) ^ bsw) << 4)), bf);
                    hmma(acc[0][2 * np],     afr[k][0], bf);
                    hmma(acc[0][2 * np + 1], afr[k][0], bf + 2);
                    hmma(acc[1][2 * np],     afr[k][1], bf);
                    hmma(acc[1][2 * np + 1], afr[k][1], bf + 2);
                }

            #pragma unroll
            for (int np = 0; np < 4; np++) {
                const int col = o0 + np * 16 + 4 * tg;
                const float4 pl = *(const float4*)&poolp[col];
                #pragma unroll
                for (int mt = 0; mt < 2; mt++) {
                    const float* a0 = acc[mt][2 * np];
                    const float* a1 = acc[mt][2 * np + 1];
                    float* r0 = outb + (size_t)(m0 + mt * 16 + g) * Ov + col;
                    stg_cs4(r0,
                            fmaxf(a0[0] - pl.x, 0.f), fmaxf(a0[1] - pl.y, 0.f),
                            fmaxf(a1[0] - pl.z, 0.f), fmaxf(a1[1] - pl.w, 0.f));
                    stg_cs4(r0 + 8 * Ov,
                            fmaxf(a0[2] - pl.x, 0.f), fmaxf(a0[3] - pl.y, 0.f),
                            fmaxf(a1[2] - pl.z, 0.f), fmaxf(a1[3] - pl.w, 0.f));
                }
            }
        }
    }
}

extern "C" void kernel_launch(void* const* d_in, const int* in_sizes, int n_in,
                              void* d_out, int out_size)
{
    (void)in_sizes; (void)n_in; (void)out_size;
    const float* x   = (const float*)d_in[0];
    const float* lam = (const float*)d_in[1];
    const float* gam = (const float*)d_in[2];
    float* out = (float*)d_out;

    cudaFuncSetAttribute(eq_mma10_kernel, cudaFuncAttributeMaxDynamicSharedMemorySize,
                         SMEM_BYTES);
    eq_mma10_kernel<<<Bv, 256, SMEM_BYTES>>>(x, lam, gam, out);
}

// round 15
// speedup vs baseline: 1.2079x; 1.0115x over previous
#include <cuda_runtime.h>
#include <cstdint>

#define Bv 8192
#define Mv 512
#define Ov 128
#define NCONC 296   // 148 SMs x 2 CTAs/SM = one wave

// ---- smem byte offsets ----
#define SM_XH   0        // x bf16: 512 rows * 128B (chunk-XOR swizzled) = 65536
#define SM_LN   65536    // lam^T bf16 (o-row-permuted): 128 rows * 128B = 16384
#define SM_SRED 81920    // 16 x 64 f32 partial column sums = 4096
#define SM_POOL 86016    // pooled[128] f32 = 512
#define SMEM_BYTES 86528

__device__ __forceinline__ uint32_t cvta_smem(const void* p) {
    uint32_t a;
    asm("{ .reg .u64 t; cvta.to.shared.u64 t, %1; cvt.u32.u64 %0, t; }" : "=r"(a) : "l"(p));
    return a;
}

__device__ __forceinline__ uint32_t pack_bf16x2(float lo, float hi) {
    uint32_t r;
    asm("cvt.rn.bf16x2.f32 %0, %1, %2;" : "=r"(r) : "f"(hi), "f"(lo));
    return r;
}

__device__ __forceinline__ void ldsm4(uint32_t addr, uint32_t r[4]) {
    asm volatile("ldmatrix.sync.aligned.m8n8.x4.shared.b16 {%0,%1,%2,%3}, [%4];"
        : "=r"(r[0]), "=r"(r[1]), "=r"(r[2]), "=r"(r[3]) : "r"(addr));
}

__device__ __forceinline__ void hmma(float d[4], const uint32_t a[4], const uint32_t b[2]) {
    asm volatile("mma.sync.aligned.m16n8k16.row.col.f32.bf16.bf16.f32 "
        "{%0,%1,%2,%3}, {%4,%5,%6,%7}, {%8,%9}, {%0,%1,%2,%3};"
        : "+f"(d[0]), "+f"(d[1]), "+f"(d[2]), "+f"(d[3])
        : "r"(a[0]), "r"(a[1]), "r"(a[2]), "r"(a[3]), "r"(b[0]), "r"(b[1]));
}

__device__ __forceinline__ float4 ldg_cs4(const float4* p) {
    float4 v;
    asm volatile("ld.global.cs.v4.f32 {%0,%1,%2,%3}, [%4];"
        : "=f"(v.x), "=f"(v.y), "=f"(v.z), "=f"(v.w) : "l"(p));
    return v;
}
__device__ __forceinline__ void stg_cs4(float* p, float a, float b, float c, float d) {
    asm volatile("st.global.cs.v4.f32 [%0], {%1,%2,%3,%4};"
        :: "l"(p), "f"(a), "f"(b), "f"(c), "f"(d) : "memory");
}

// forced L2 fill: real 256-bit read (sm_103 requires .v8.b32 with evict_last),
// result discarded; evict_last keeps lines resident across streaming stores.
__device__ __forceinline__ void l2fill(const void* p) {
    uint32_t r0, r1, r2, r3, r4, r5, r6, r7;
    asm volatile("ld.global.L2::evict_last.v8.b32 {%0,%1,%2,%3,%4,%5,%6,%7}, [%8];"
        : "=r"(r0), "=r"(r1), "=r"(r2), "=r"(r3),
          "=r"(r4), "=r"(r5), "=r"(r6), "=r"(r7)
        : "l"(p));
}

extern __shared__ char smem[];

__global__ __launch_bounds__(256, 2)
void eq_mma12_kernel(const float* __restrict__ x,
                     const float* __restrict__ lam,
                     const float* __restrict__ gam,
                     float* __restrict__ out)
{
    const uint32_t sb = cvta_smem(smem);
    const int t = threadIdx.x;
    const int b = blockIdx.x;
    const int w = t >> 5, lane = t & 31, g = lane >> 2, tg = lane & 3;

    // ---- Phase A: x[b] fp32 -> bf16 smem (swizzled) + partial column sums ----
    {
        const float4* xg = (const float4*)(x + (size_t)b * (Mv * 64));
        const int f4 = t & 15;            // which float4 within a row
        const int tm = t >> 4;            // row phase (0..15)
        const int chunk = f4 >> 1, half = f4 & 1;
        float4 s4 = make_float4(0.f, 0.f, 0.f, 0.f);
        #pragma unroll 8
        for (int i = 0; i < 32; i++) {
            const int m = tm + 16 * i;
            const float4 v = ldg_cs4(&xg[m * 16 + f4]);
            s4.x += v.x; s4.y += v.y; s4.z += v.z; s4.w += v.w;
            const uint32_t h01 = pack_bf16x2(v.x, v.y);
            const uint32_t h23 = pack_bf16x2(v.z, v.w);
            const uint32_t off = (uint32_t)(m * 128 + ((chunk ^ (m & 7)) << 4) + half * 8);
            *(uint2*)(smem + SM_XH + off) = make_uint2(h01, h23);
        }
        *(float4*)(smem + SM_SRED + (tm * 64 + f4 * 4) * 4) = s4;
    }

    // ---- force next wave's x[b+NCONC] into L2 (reads overlap store phase) ----
    if (b + NCONC < Bv) {
        const char* nx = (const char*)(x + (size_t)(b + NCONC) * (Mv * 64));
        #pragma unroll
        for (int j = 0; j < 4; j++)
            l2fill(nx + (t + 256 * j) * 128);
    }

    // ---- Phase B: lam^T -> bf16 smem, o-row-permuted within 16-row groups ----
    {
        const int o = t & 127;
        const int r15 = o & 15;
        const int orow = (o & ~15) | (((r15 & 2) << 2) | ((r15 >> 2) << 1) | (r15 & 1));
        const int q = t >> 7;
        #pragma unroll 4
        for (int j = 0; j < 16; j++) {
            const int fp = q * 16 + j;
            const float v0 = lam[(2 * fp) * Ov + o];
            const float v1 = lam[(2 * fp + 1) * Ov + o];
            const uint32_t h = pack_bf16x2(v0, v1);
            const uint32_t off = (uint32_t)(orow * 128
                + (((fp >> 2) ^ (orow & 7)) << 4) + (fp & 3) * 4);
            *(uint32_t*)(smem + SM_LN + off) = h;
        }
    }
    __syncthreads();

    // ---- finalize s[f] = sum_m x[m,f] ----
    if (t < 64) {
        float v = 0.f;
        #pragma unroll
        for (int r = 0; r < 16; r++)
            v += *(const float*)(smem + SM_SRED + (r * 64 + t) * 4);
        *(float*)(smem + SM_SRED + t * 4) = v;
    }
    __syncthreads();

    // ---- pooled[o] = sum_f s[f] * gam[f,o] (exact fp32) ----
    if (t < 128) {
        float p = 0.f;
        #pragma unroll
        for (int f = 0; f < 64; f++)
            p += *(const float*)(smem + SM_SRED + f * 4) * gam[f * Ov + t];
        *(float*)(smem + SM_POOL + t * 4) = p;
    }
    __syncthreads();

    // ---- Main: per-warp 64 rows x 128 cols, two 32-row sub-passes ----
    const int am = lane & 15, acs = lane >> 4, asw = am & 7;
    const int bo = (lane & 7) | ((lane & 16) >> 1);
    const int bcs = (lane >> 3) & 1, bsw = bo & 7;
    const float* poolp = (const float*)(smem + SM_POOL);
    float* outb = out + (size_t)b * (Mv * Ov);

    #pragma unroll 1
    for (int mp = 0; mp < 2; mp++) {
        const int m0 = w * 64 + mp * 32;
        const uint32_t arow_off = (uint32_t)((m0 + am) * 128);

        uint32_t afr[4][2][4];
        #pragma unroll
        for (int k = 0; k < 4; k++) {
            const uint32_t aadr = sb + SM_XH + arow_off
                                + (uint32_t)((((k << 1) | acs) ^ asw) << 4);
            ldsm4(aadr, afr[k][0]);
            ldsm4(aadr + 16 * 128, afr[k][1]);
        }

        #pragma unroll 1
        for (int nh = 0; nh < 2; nh++) {
            const int o0 = nh * 64;
            float acc[2][8][4];
            #pragma unroll
            for (int i = 0; i < 2; i++)
                #pragma unroll
                for (int j = 0; j < 8; j++)
                    #pragma unroll
                    for (int c = 0; c < 4; c++)
                        acc[i][j][c] = 0.f;

            #pragma unroll
            for (int k = 0; k < 4; k++)
                #pragma unroll
                for (int np = 0; np < 4; np++) {
                    uint32_t bf[4];
                    ldsm4(sb + SM_LN + (uint32_t)((o0 + np * 16 + bo) * 128
                            + ((((k << 1) | bcs) ^ bsw) << 4)), bf);
                    hmma(acc[0][2 * np],     afr[k][0], bf);
                    hmma(acc[0][2 * np + 1], afr[k][0], bf + 2);
                    hmma(acc[1][2 * np],     afr[k][1], bf);
                    hmma(acc[1][2 * np + 1], afr[k][1], bf + 2);
                }

            #pragma unroll
            for (int np = 0; np < 4; np++) {
                const int col = o0 + np * 16 + 4 * tg;
                const float4 pl = *(const float4*)&poolp[col];
                #pragma unroll
                for (int mt = 0; mt < 2; mt++) {
                    const float* a0 = acc[mt][2 * np];
                    const float* a1 = acc[mt][2 * np + 1];
                    float* r0 = outb + (size_t)(m0 + mt * 16 + g) * Ov + col;
                    stg_cs4(r0,
                            fmaxf(a0[0] - pl.x, 0.f), fmaxf(a0[1] - pl.y, 0.f),
                            fmaxf(a1[0] - pl.z, 0.f), fmaxf(a1[1] - pl.w, 0.f));
                    stg_cs4(r0 + 8 * Ov,
                            fmaxf(a0[2] - pl.x, 0.f), fmaxf(a0[3] - pl.y, 0.f),
                            fmaxf(a1[2] - pl.z, 0.f), fmaxf(a1[3] - pl.w, 0.f));
                }
            }
        }
    }
}

extern "C" void kernel_launch(void* const* d_in, const int* in_sizes, int n_in,
                              void* d_out, int out_size)
{
    (void)in_sizes; (void)n_in; (void)out_size;
    const float* x   = (const float*)d_in[0];
    const float* lam = (const float*)d_in[1];
    const float* gam = (const float*)d_in[2];
    float* out = (float*)d_out;

    cudaFuncSetAttribute(eq_mma12_kernel, cudaFuncAttributeMaxDynamicSharedMemorySize,
                         SMEM_BYTES);
    eq_mma12_kernel<<<Bv, 256, SMEM_BYTES>>>(x, lam, gam, out);
}